// round 1
// baseline (speedup 1.0000x reference)
#include <cuda_runtime.h>

// AllPassFilterAugmentation: biquad allpass, fs=16000, f0=4000, Q=0.707.
// w0 = pi/2 -> a1,b1 ~ 6e-17, b2/a0 = 1, b0/a0 = a2/a0 = c.
// Coefficients (double-precision math, matching the numpy reference, then f32):
#define C_B0 0.17149858514250882f
#define C_B1 (-7.173268854272228e-17f)
#define C_B2 1.0f
#define C_A1 (-7.173268854272228e-17f)
#define C_A2 0.17149858514250882f

#define THREADS 128
#define L_OUT   32                    // outputs per thread
#define TILE    (THREADS * L_OUT)     // 4096 samples per block
#define WARM    24                    // zero-state warmup samples (err ~ 0.1716^12 = 6e-10)
#define PRE     (WARM + 2)            // warmup + 2 samples of x-history = 26

// smem skew to kill 32-way bank conflicts from 128B per-thread stride
#define SKEW(i) ((i) + ((i) >> 5))

__global__ __launch_bounds__(THREADS)
void allpass_biquad_kernel(const float* __restrict__ x,
                           float* __restrict__ y,
                           int T)
{
    __shared__ float s_in [TILE + PRE + ((TILE + PRE) >> 5) + 1];
    __shared__ float s_out[TILE + (TILE >> 5) + 1];

    const int       seq    = blockIdx.y;
    const long long base   = (long long)seq * (long long)T;
    const int       tstart = blockIdx.x * TILE;

    // ---- stage input: logical i in [0, TILE+PRE) maps to global tstart - PRE + i
    for (int i = threadIdx.x; i < TILE + PRE; i += THREADS) {
        int g = tstart - PRE + i;
        float v = 0.0f;
        if (g >= 0 && g < T) v = __ldg(x + base + g);
        s_in[SKEW(i)] = v;
    }
    __syncthreads();

    // ---- per-thread serial biquad over its 32-sample chunk (+24 warmup)
    {
        // thread tid owns logical s_in indices [tid*32, tid*32 + PRE + 31].
        // Since tid*32 is a multiple of 32: SKEW(tid*32 + d) == 33*tid + d + (d>>5),
        // so all offsets below are compile-time immediates after unroll.
        const int sb = threadIdx.x * 33;

        float x2 = s_in[sb + 0];
        float x1 = s_in[sb + 1];
        float y1 = 0.0f, y2 = 0.0f;

        // warmup: d = 2 .. PRE-1  (global samples tstart + tid*32 - WARM .. -1)
        #pragma unroll
        for (int d = 2; d < PRE; ++d) {
            float xn = s_in[sb + d + (d >> 5)];
            float yn = C_B0 * xn + C_B1 * x1 + C_B2 * x2 - C_A1 * y1 - C_A2 * y2;
            x2 = x1; x1 = xn; y2 = y1; y1 = yn;
        }

        // main: 32 outputs
        const int ob = threadIdx.x * 33;  // SKEW(tid*32 + t) = 33*tid + t for t<32
        #pragma unroll
        for (int t = 0; t < L_OUT; ++t) {
            const int d = PRE + t;
            float xn = s_in[sb + d + (d >> 5)];
            float yn = C_B0 * xn + C_B1 * x1 + C_B2 * x2 - C_A1 * y1 - C_A2 * y2;
            s_out[ob + t] = yn;
            x2 = x1; x1 = xn; y2 = y1; y1 = yn;
        }
    }
    __syncthreads();

    // ---- coalesced store
    for (int i = threadIdx.x; i < TILE; i += THREADS) {
        int g = tstart + i;
        if (g < T) y[base + g] = s_out[SKEW(i)];
    }
}

extern "C" void kernel_launch(void* const* d_in, const int* in_sizes, int n_in,
                              void* d_out, int out_size)
{
    const float* x = (const float*)d_in[0];
    float*       y = (float*)d_out;

    const int B = 64;                      // fixed problem shape [64, 1, 480000]
    const int T = in_sizes[0] / B;         // 480000

    const int tiles = (T + TILE - 1) / TILE;
    dim3 grid(tiles, B, 1);
    allpass_biquad_kernel<<<grid, THREADS>>>(x, y, T);
}

// round 3
// speedup vs baseline: 1.3812x; 1.3812x over previous
#include <cuda_runtime.h>

// Allpass biquad, fs=16000, f0=4000, Q=0.707. w0 = pi/2 exactly ->
// cos(w0) ~ 6e-17 -> b1 = a1 ~ 0 (dropped; ~1e-16 relative contribution).
//   y[n] = c*x[n] + x[n-2] - c*y[n-2],  c = (1-alpha)/(1+alpha)
#define C_B0 0.17149858514250882f
#define C_A2 0.17149858514250882f

#define THREADS 256
#define L_OUT   16
#define TILE    (THREADS * L_OUT)     // 4096 samples per block
#define WARM    30                    // zero-state warmup (err ~ 0.1716^15 = 3e-12)
#define PRE     (WARM + 2)            // 32

// smem skew at scalar granularity: stride between threads' chunks = 17 floats
// (odd -> conflict-free scalar LDS). Stores into it are scalar (no alignment req).
#define SKEW(i) ((i) + ((i) >> 4))

#define S_IN_SZ (TILE + PRE + ((TILE + PRE) >> 4) + 2)

__global__ __launch_bounds__(THREADS)
void allpass_biquad_kernel(const float* __restrict__ x,
                           float* __restrict__ y,
                           int T)
{
    __shared__ float s_in[S_IN_SZ];

    const long long base   = (long long)blockIdx.y * (long long)T;
    const int       tstart = blockIdx.x * TILE;
    const int       tid    = threadIdx.x;

    // ---- stage input: vector LDG (aligned), scalar STS (skewed).
    // Logical float i in [0, TILE+PRE) = global sample tstart - PRE + i.
    {
        const int       NV    = (TILE + PRE) / 4;   // 1032 float4s
        const int       gv0   = (tstart >> 2) - (PRE / 4);
        const int       TV    = T >> 2;
        const long long base4 = base >> 2;
        const float4*   x4    = (const float4*)x;

        #pragma unroll
        for (int v = tid; v < NV; v += THREADS) {
            int gv = gv0 + v;
            float4 val = make_float4(0.f, 0.f, 0.f, 0.f);
            if (gv >= 0 && gv < TV) val = __ldg(x4 + base4 + gv);
            // SKEW(4v+j) = 4v + j + (v>>2) for j in 0..3 (no group boundary crossed)
            int s = 4 * v + (v >> 2);
            s_in[s + 0] = val.x;
            s_in[s + 1] = val.y;
            s_in[s + 2] = val.z;
            s_in[s + 3] = val.w;
        }
    }
    __syncthreads();

    // ---- per-thread serial biquad: 30 warmup + 16 outputs, stored as 4x STG.128.
    {
        const bool valid = (tstart + tid * L_OUT + L_OUT) <= T;  // all-or-nothing
        const int  sb    = tid * 17;        // SKEW(tid*16) ; offsets below immediate
        float*     yo    = y + base + tstart + tid * L_OUT;

        float x2 = s_in[sb + 0];
        float x1 = s_in[sb + 1];
        float y1 = 0.f, y2 = 0.f;
        float4 o;

        #pragma unroll
        for (int d = 2; d < PRE + L_OUT; ++d) {
            float xn = s_in[sb + d + (d >> 4)];
            float t  = fmaf(C_B0, xn, x2);       // off the dependent chain
            float yn = fmaf(-C_A2, y2, t);       // 1 FFMA on the y2 chain
            if (d >= PRE) {
                const int idx = d - PRE;
                if ((idx & 3) == 0) o.x = yn;
                else if ((idx & 3) == 1) o.y = yn;
                else if ((idx & 3) == 2) o.z = yn;
                else {
                    o.w = yn;
                    if (valid) *(float4*)(yo + (idx - 3)) = o;
                }
            }
            x2 = x1; x1 = xn; y2 = y1; y1 = yn;
        }
    }
}

extern "C" void kernel_launch(void* const* d_in, const int* in_sizes, int n_in,
                              void* d_out, int out_size)
{
    const float* x = (const float*)d_in[0];
    float*       y = (float*)d_out;

    const int B = 64;                  // fixed shape [64, 1, 480000]
    const int T = in_sizes[0] / B;

    const int tiles = (T + TILE - 1) / TILE;
    dim3 grid(tiles, B, 1);
    allpass_biquad_kernel<<<grid, THREADS>>>(x, y, T);
}

// round 4
// speedup vs baseline: 1.7797x; 1.2886x over previous
#include <cuda_runtime.h>

// Allpass biquad, fs=16000, f0=4000, Q=0.707. w0 = pi/2 exactly ->
// normalized coeffs: b0 = a2 = c, b2 = 1, b1 = a1 ~ 6e-17 (dropped).
//
// Closed FIR form:  H(z) = (c + z^-2)/(1 + c z^-2)
//                        = c + (1-c^2) * sum_{m>=0} (-c)^m z^(-2-2m)
// Truncated at m=9 (tail ~ c^10 = 2.2e-8 << 1e-3 tolerance):
//   y[n] = c*x[n] + (1-c^2) * S[n],   S[n] = sum_{m=0..9} (-c)^m x[n-2-2m]
// Fully parallel: no scan, no warmup, no shared memory.

#define C_C   0.17149858514250882f
#define C_CN  (-0.17149858514250882f)
#define C_OM  0.97058823630252067f   /* 1 - c^2 */

#define THREADS 256
#define L_OUT   8                       // outputs per thread
#define TILE    (THREADS * L_OUT)       // 2048 samples per block
#define NTAPS   10                      // m = 0..9
#define WIN     28                      // floats [n0-20, n0+8) ; 7 float4s

__global__ __launch_bounds__(THREADS)
void allpass_fir_kernel(const float* __restrict__ x,
                        float* __restrict__ y,
                        int T)
{
    const int       tid  = threadIdx.x;
    const long long base = (long long)blockIdx.y * (long long)T;
    const int       n0   = blockIdx.x * TILE + tid * L_OUT;

    // ---- load 28-float window [n0-20, n0+8) as 7 float4 (16B-aligned: n0%8==0)
    const int     gv0 = (n0 - 20) >> 2;     // may be negative at sequence start
    const int     TV  = T >> 2;
    const float4* x4  = (const float4*)(x + base);

    float W[WIN];
    #pragma unroll
    for (int j = 0; j < WIN / 4; ++j) {
        const int gv = gv0 + j;
        float4 v = make_float4(0.f, 0.f, 0.f, 0.f);
        if (gv >= 0 && gv < TV) v = __ldg(x4 + gv);
        W[4 * j + 0] = v.x;
        W[4 * j + 1] = v.y;
        W[4 * j + 2] = v.z;
        W[4 * j + 3] = v.w;
    }

    // ---- S[0], S[1] by Horner over 10 taps (independent even/odd chains)
    //      S[i] for n0+i uses x[n0+i-2-2m] = W[18+i-2m]
    float S0 = W[0];                 // m=9 term for i=0
    float S1 = W[1];                 // m=9 term for i=1
    #pragma unroll
    for (int m = 8; m >= 0; --m) {
        S0 = fmaf(C_CN, S0, W[18 - 2 * m]);
        S1 = fmaf(C_CN, S1, W[19 - 2 * m]);
    }

    // ---- remaining S by 1-FMA recurrence: S[i] = W[18+i] - c*S[i-2]
    float S[L_OUT];
    S[0] = S0; S[1] = S1;
    #pragma unroll
    for (int i = 2; i < L_OUT; ++i)
        S[i] = fmaf(C_CN, S[i - 2], W[18 + i]);

    // ---- outputs: y[n0+i] = c*x[n0+i] + (1-c^2)*S[i]
    float4 o0, o1;
    o0.x = fmaf(C_C, W[20], C_OM * S[0]);
    o0.y = fmaf(C_C, W[21], C_OM * S[1]);
    o0.z = fmaf(C_C, W[22], C_OM * S[2]);
    o0.w = fmaf(C_C, W[23], C_OM * S[3]);
    o1.x = fmaf(C_C, W[24], C_OM * S[4]);
    o1.y = fmaf(C_C, W[25], C_OM * S[5]);
    o1.z = fmaf(C_C, W[26], C_OM * S[6]);
    o1.w = fmaf(C_C, W[27], C_OM * S[7]);

    if (n0 + L_OUT <= T) {               // all-or-nothing: T % 8 == 0
        float4* yo = (float4*)(y + base + n0);
        yo[0] = o0;
        yo[1] = o1;
    }
}

extern "C" void kernel_launch(void* const* d_in, const int* in_sizes, int n_in,
                              void* d_out, int out_size)
{
    const float* x = (const float*)d_in[0];
    float*       y = (float*)d_out;

    const int B = 64;                    // fixed shape [64, 1, 480000]
    const int T = in_sizes[0] / B;

    const int tiles = (T + TILE - 1) / TILE;
    dim3 grid(tiles, B, 1);
    allpass_fir_kernel<<<grid, THREADS>>>(x, y, T);
}